// round 11
// baseline (speedup 1.0000x reference)
#include <cuda_runtime.h>
#include <cstdint>

// ---------------- problem constants ----------------
#define D_DIM    64
#define SUBN     256
#define T_LEN    16384
#define N_ROWS   262144
#define ZQ_ELEMS 16777216
#define LOSS_OFF ZQ_ELEMS
#define PERP_OFF (ZQ_ELEMS + 1)
#define IDX_OFF  (ZQ_ELEMS + 2)
#define NTILES   1024          // 256 rows per tile
#define LCAP     16            // per-row candidate list capacity

// ---------------- persistent scratch ----------------
// Invariant: all zero at kernel_launch entry; finalizer re-zeros.
__device__ int          g_counts[SUBN];
__device__ double       g_sse;
__device__ unsigned int g_done;
__device__ unsigned int g_tick;

// ---------------- helpers --------------------------
__device__ __forceinline__ unsigned long long ffma2(unsigned long long a,
                                                    unsigned long long b,
                                                    unsigned long long c) {
    unsigned long long d;
    asm("fma.rn.f32x2 %0, %1, %2, %3;" : "=l"(d) : "l"(a), "l"(b), "l"(c));
    return d;
}
__device__ __forceinline__ float2 unpack2(unsigned long long v) {
    float2 r;
    asm("mov.b64 {%0, %1}, %2;" : "=f"(r.x), "=f"(r.y) : "l"(v));
    return r;
}
__device__ __forceinline__ unsigned long long pack64(float lo, float hi) {
    unsigned long long v;
    asm("mov.b64 %0, {%1, %2};" : "=l"(v) : "f"(lo), "f"(hi));
    return v;
}
__device__ __forceinline__ unsigned long long packdj(float d, int j) {
    return ((unsigned long long)__float_as_uint(d) << 32) | (unsigned)j;
}
__device__ __forceinline__ uint32_t pack4b(int b0, int b1, int b2, int b3) {
    return (uint32_t)(b0 & 255) | ((uint32_t)(b1 & 255) << 8) |
           ((uint32_t)(b2 & 255) << 16) | ((uint32_t)(b3 & 255) << 24);
}

// int8 filter score: s = ee[j] - 2*dot  (approximate; rescue makes it exact)
__device__ __forceinline__ float filt_s(const uint4* __restrict__ Eq4,
                                        const uint32_t* qz,
                                        float eej, float negc2, int j) {
    int a0 = 0, a1 = 0, a2 = 0, a3 = 0;
    #pragma unroll
    for (int c = 0; c < 4; c++) {
        uint4 v = Eq4[j * 4 + c];
        a0 = __dp4a((int)v.x, (int)qz[c * 4 + 0], a0);
        a1 = __dp4a((int)v.y, (int)qz[c * 4 + 1], a1);
        a2 = __dp4a((int)v.z, (int)qz[c * 4 + 2], a2);
        a3 = __dp4a((int)v.w, (int)qz[c * 4 + 3], a3);
    }
    float dotf = (float)((a0 + a1) + (a2 + a3));
    return fmaf(dotf, negc2, eej);
}

// R1's exact fp32 distance: packed ffma2 dual-chain dot, (zz+ee) - 2*dot
__device__ __forceinline__ float exact_dg(const unsigned long long* z2, float zz,
                                          const float* __restrict__ erow,
                                          float eej) {
    unsigned long long a0 = 0ull, a1 = 0ull;
    const float4* e4 = (const float4*)erow;
    #pragma unroll
    for (int i = 0; i < 16; i++) {
        float4 e = __ldg(e4 + i);
        a0 = ffma2(z2[2 * i],     pack64(e.x, e.y), a0);
        a1 = ffma2(z2[2 * i + 1], pack64(e.z, e.w), a1);
    }
    float2 x0 = unpack2(a0), x1 = unpack2(a1);
    const float dot = (x0.x + x0.y) + (x1.x + x1.y);
    return (zz + eej) - 2.0f * dot;
}

// ==================================================================
__global__ __launch_bounds__(256, 2) void vq_dp4a(const float* __restrict__ z,
                                                  const float* __restrict__ one_hot,
                                                  const float* __restrict__ W,
                                                  float* __restrict__ out,
                                                  int nblocks) {
    __shared__ uint4    Eq[SUBN * 4];          // int8 codebook, 16KB
    __shared__ float    ee[SUBN];
    __shared__ uint32_t slist[SUBN * LCAP];    // candidate j lists, 16KB
    __shared__ int      shist[SUBN];
    __shared__ float    sred[8];
    __shared__ float    emax_r[8];
    __shared__ float    sEMAX;
    __shared__ unsigned stile;

    const int tid  = threadIdx.x;
    const int lane = tid & 31;
    const int w    = tid >> 5;

    // pos = argmax(one_hot), first-max semantics
    float mv = one_hot[0];
    int pos = 0;
    #pragma unroll
    for (int i = 1; i < 7; i++) {
        float v = one_hot[i];
        if (v > mv) { mv = v; pos = i; }
    }
    const float* Wp = W + (size_t)pos * SUBN * D_DIM;

    // ---- E prep: ee (exact R1 chain) + block max|e| ----
    float4 ebuf[16];
    {
        const float4* er4 = (const float4*)(Wp + (size_t)tid * D_DIM);
        #pragma unroll
        for (int i = 0; i < 16; i++) ebuf[i] = __ldg(er4 + i);
        float s = 0.f, me = 0.f;
        #pragma unroll
        for (int i = 0; i < 16; i++) {
            s = fmaf(ebuf[i].x, ebuf[i].x, s);
            s = fmaf(ebuf[i].y, ebuf[i].y, s);
            s = fmaf(ebuf[i].z, ebuf[i].z, s);
            s = fmaf(ebuf[i].w, ebuf[i].w, s);
            me = fmaxf(me, fabsf(ebuf[i].x));
            me = fmaxf(me, fabsf(ebuf[i].y));
            me = fmaxf(me, fabsf(ebuf[i].z));
            me = fmaxf(me, fabsf(ebuf[i].w));
        }
        ee[tid] = s;
        #pragma unroll
        for (int o = 16; o > 0; o >>= 1)
            me = fmaxf(me, __shfl_xor_sync(0xffffffffu, me, o));
        if (lane == 0) emax_r[w] = me;
        shist[tid] = 0;
    }
    __syncthreads();
    if (tid == 0) {
        float m = emax_r[0];
        #pragma unroll
        for (int q = 1; q < 8; q++) m = fmaxf(m, emax_r[q]);
        sEMAX = fmaxf(m, 1e-30f);
    }
    __syncthreads();

    const float EMAXE = sEMAX;
    const float SE = 127.0f / EMAXE;
    const float he = 0.5f / SE;

    // quantize E into smem int8 tiles
    {
        uint32_t eq[16];
        #pragma unroll
        for (int i = 0; i < 16; i++) {
            eq[i] = pack4b(__float2int_rn(ebuf[i].x * SE),
                           __float2int_rn(ebuf[i].y * SE),
                           __float2int_rn(ebuf[i].z * SE),
                           __float2int_rn(ebuf[i].w * SE));
        }
        #pragma unroll
        for (int c = 0; c < 4; c++)
            Eq[tid * 4 + c] = make_uint4(eq[4 * c], eq[4 * c + 1],
                                         eq[4 * c + 2], eq[4 * c + 3]);
    }
    __syncthreads();

    float sse_loc = 0.f;

    // ---- main loop: global work ticket over 1024 tiles of 256 rows ----
    while (true) {
        __syncthreads();
        if (tid == 0) stile = atomicAdd(&g_tick, 1u);
        __syncthreads();
        const unsigned tile = stile;
        if (tile >= NTILES) break;

        const int n = (int)tile * 256 + tid;     // this thread's row

        // load z row; exact zz (R1 chain); per-row quant scale + margin terms
        unsigned long long z2[32];
        uint32_t qz[16];
        float zz, sumabs, SZ;
        {
            const float4* zp = (const float4*)(z + (size_t)n * D_DIM);
            float4 zb[16];
            #pragma unroll
            for (int i = 0; i < 16; i++) zb[i] = __ldg(zp + i);
            unsigned long long zzacc = 0ull;
            float sa = 0.f, mz = 0.f;
            #pragma unroll
            for (int i = 0; i < 16; i++) {
                unsigned long long vx = pack64(zb[i].x, zb[i].y);
                unsigned long long vy = pack64(zb[i].z, zb[i].w);
                z2[2 * i] = vx; z2[2 * i + 1] = vy;
                zzacc = ffma2(vx, vx, zzacc);
                zzacc = ffma2(vy, vy, zzacc);
                sa += fabsf(zb[i].x) + fabsf(zb[i].y) +
                      fabsf(zb[i].z) + fabsf(zb[i].w);
                mz = fmaxf(mz, fmaxf(fmaxf(fabsf(zb[i].x), fabsf(zb[i].y)),
                                     fmaxf(fabsf(zb[i].z), fabsf(zb[i].w))));
            }
            float2 p = unpack2(zzacc);
            zz = p.x + p.y;
            sumabs = sa;
            SZ = 127.0f / fmaxf(mz, 1e-30f);
            #pragma unroll
            for (int i = 0; i < 16; i++) {
                qz[i] = pack4b(__float2int_rn(zb[i].x * SZ),
                               __float2int_rn(zb[i].y * SZ),
                               __float2int_rn(zb[i].z * SZ),
                               __float2int_rn(zb[i].w * SZ));
            }
        }
        const float hz    = 0.5f / SZ;
        const float negc2 = -2.0f / (SZ * SE);
        // rigorous rescue margin: 4*eps_dot + slop
        const float marg  = 4.0f * (he * sumabs + 64.0f * hz * (EMAXE + he))
                            + 1e-6f;

        // seed running best with 8 strided probes (reduces list pressure)
        float best = 3.402823466e38f;
        #pragma unroll
        for (int t = 0; t < 8; t++) {
            float s = filt_s(Eq, qz, ee[t * 32 + 16], negc2, t * 32 + 16);
            best = fminf(best, s);
        }

        // filter scan: log candidates within running_best + marg
        int cnt = 0;
        #pragma unroll 2
        for (int j = 0; j < SUBN; j++) {
            float s = filt_s(Eq, qz, ee[j], negc2, j);
            if (s <= best + marg) {
                if (cnt < LCAP) slist[tid * LCAP + cnt] = (uint32_t)j;
                cnt++;
            }
            best = fminf(best, s);
        }

        // resolve with the exact R1 chain
        unsigned long long rb = ~0ull;
        if (cnt > LCAP) {
            for (int j = 0; j < SUBN; j++) {
                float de = exact_dg(z2, zz, Wp + (size_t)j * D_DIM, ee[j]);
                unsigned long long p = packdj(de, j);
                if (p < rb) rb = p;
            }
        } else {
            for (int i = 0; i < cnt; i++) {
                int j = (int)slist[tid * LCAP + i];
                float de = exact_dg(z2, zz, Wp + (size_t)j * D_DIM, ee[j]);
                unsigned long long p = packdj(de, j);
                if (p < rb) rb = p;
            }
        }
        const int   jwin = (int)(rb & 0xffffffffu);
        const float dwin = __uint_as_float((uint32_t)(rb >> 32));

        atomicAdd(&shist[jwin], 1);
        sse_loc += dwin;                        // exact ||z - e||^2 (R1 chain)
        out[IDX_OFF + n] = (float)jwin;

        // z_q transposed write: e row to regs, then 64 coalesced STG
        {
            const float4* er4 = (const float4*)(Wp + (size_t)jwin * D_DIM);
            const int b = n >> 14, t = n & (T_LEN - 1);
            float* ob = out + (size_t)b * D_DIM * T_LEN + t;
            #pragma unroll
            for (int i = 0; i < 16; i++) {
                float4 e = __ldg(er4 + i);
                ob[(size_t)(4 * i + 0) * T_LEN] = e.x;
                ob[(size_t)(4 * i + 1) * T_LEN] = e.y;
                ob[(size_t)(4 * i + 2) * T_LEN] = e.z;
                ob[(size_t)(4 * i + 3) * T_LEN] = e.w;
            }
        }
    }

    // ---- block reductions + global flush ----
    __syncthreads();
    float s = sse_loc;
    #pragma unroll
    for (int o = 16; o > 0; o >>= 1)
        s += __shfl_down_sync(0xffffffffu, s, o);
    if (lane == 0) sred[w] = s;
    __syncthreads();
    if (tid == 0) {
        float tot = 0.f;
        #pragma unroll
        for (int q = 0; q < 8; q++) tot += sred[q];
        atomicAdd(&g_sse, (double)tot);
    }
    atomicAdd(&g_counts[tid], shist[tid]);

    // ---- last-block finalize ----
    __threadfence();
    __syncthreads();
    if (tid == 0) stile = atomicAdd(&g_done, 1u);
    __syncthreads();
    if (stile == (unsigned)(nblocks - 1)) {
        float c = (float)g_counts[tid];
        g_counts[tid] = 0;                      // restore zero-invariant
        float em = c * (1.0f / 262144.0f);
        float v = em * logf(em + 1e-10f);
        #pragma unroll
        for (int o = 16; o > 0; o >>= 1)
            v += __shfl_down_sync(0xffffffffu, v, o);
        if (lane == 0) sred[w] = v;
        __syncthreads();
        if (tid == 0) {
            float H = 0.f;
            #pragma unroll
            for (int q = 0; q < 8; q++) H += sred[q];
            out[PERP_OFF] = expf(-H);
            double sse = g_sse;
            g_sse = 0.0;
            float m = (float)(sse * (1.0 / 16777216.0));
            out[LOSS_OFF] = 0.25f * m + m;      // BETA*mse + mse
            g_tick = 0;                          // restore for next replay
            g_done = 0;
        }
    }
}

// ------------------------------------------------------------------
extern "C" void kernel_launch(void* const* d_in, const int* in_sizes, int n_in,
                              void* d_out, int out_size) {
    const float* z       = (const float*)d_in[0];
    const float* one_hot = (const float*)d_in[1];
    const float* W       = (const float*)d_in[2];
    float* out           = (float*)d_out;

    int nsm = 148;
    cudaDeviceGetAttribute(&nsm, cudaDevAttrMultiProcessorCount, 0);
    if (nsm <= 0) nsm = 148;
    const int nblocks = nsm * 2;

    vq_dp4a<<<nblocks, 256>>>(z, one_hot, W, out, nblocks);
}